// round 1
// baseline (speedup 1.0000x reference)
#include <cuda_runtime.h>

// Problem constants
#define B_  2
#define S_  2048
#define D_  1024
#define H_  16
#define HD_ 64
#define N3_ 3072
#define M_  (B_ * S_)   // 4096

// Scratch for the fused KQV projection output: [M_, 3072], layout [3][H][64] per row.
__device__ float g_kqv[(size_t)M_ * N3_];

typedef unsigned long long ull;

__device__ __forceinline__ ull pack2(float lo, float hi) {
    ull r; asm("mov.b64 %0, {%1,%2};" : "=l"(r) : "f"(lo), "f"(hi)); return r;
}
__device__ __forceinline__ void unpack2(ull v, float& lo, float& hi) {
    asm("mov.b64 {%0,%1}, %2;" : "=f"(lo), "=f"(hi) : "l"(v));
}
__device__ __forceinline__ ull fma2(ull a, ull b, ull c) {
    ull d; asm("fma.rn.f32x2 %0, %1, %2, %3;" : "=l"(d) : "l"(a), "l"(b), "l"(c)); return d;
}

// ============================================================================
// Kernel 1: C[4096,3072] = A[4096,1024] @ W[1024,3072] + bias
// 128x128 block tile, K-step 8, 256 threads, 8x8 microtile via f32x2,
// double-buffered smem (1 sync per K-iteration).
// ============================================================================
__global__ __launch_bounds__(256, 2) void gemm_kqv_kernel(
    const float* __restrict__ A, const float* __restrict__ W,
    const float* __restrict__ bias)
{
    __shared__ float As[2][8][132];   // transposed A tile: As[kk][m]
    __shared__ float Bs[2][8][128];   // Bs[kk][n]

    const int tid = threadIdx.x;
    const int tx = tid & 15, ty = tid >> 4;
    const int m0 = blockIdx.y * 128, n0 = blockIdx.x * 128;

    const int arow = tid >> 1, acol = (tid & 1) * 4;   // A: 128x8 tile
    const int brow = tid >> 5, bcol = (tid & 31) * 4;  // B: 8x128 tile

    const float* Ap = A + (size_t)(m0 + arow) * D_ + acol;
    const float* Wp = W + (size_t)brow * N3_ + n0 + bcol;

    // stage tile 0
    float4 ar = *(const float4*)Ap;
    float4 br = *(const float4*)Wp;
    As[0][acol + 0][arow] = ar.x; As[0][acol + 1][arow] = ar.y;
    As[0][acol + 2][arow] = ar.z; As[0][acol + 3][arow] = ar.w;
    *(float4*)&Bs[0][brow][bcol] = br;
    __syncthreads();

    ull acc[8][4];
    #pragma unroll
    for (int i = 0; i < 8; ++i)
        #pragma unroll
        for (int j = 0; j < 4; ++j) acc[i][j] = 0ull;

    int buf = 0;
    for (int kt = 0; kt < D_ / 8; ++kt) {
        if (kt + 1 < D_ / 8) {
            ar = *(const float4*)(Ap + (kt + 1) * 8);
            br = *(const float4*)(Wp + (size_t)(kt + 1) * 8 * N3_);
        }
        #pragma unroll
        for (int kk = 0; kk < 8; ++kk) {
            float4 a0 = *(const float4*)&As[buf][kk][ty * 8];
            float4 a1 = *(const float4*)&As[buf][kk][ty * 8 + 4];
            ull b2[4];
            #pragma unroll
            for (int j = 0; j < 4; ++j)
                b2[j] = *(const ull*)&Bs[buf][kk][tx * 8 + 2 * j];
            float av[8] = {a0.x, a0.y, a0.z, a0.w, a1.x, a1.y, a1.z, a1.w};
            #pragma unroll
            for (int i = 0; i < 8; ++i) {
                ull ad = pack2(av[i], av[i]);
                #pragma unroll
                for (int j = 0; j < 4; ++j) acc[i][j] = fma2(ad, b2[j], acc[i][j]);
            }
        }
        if (kt + 1 < D_ / 8) {
            As[buf ^ 1][acol + 0][arow] = ar.x; As[buf ^ 1][acol + 1][arow] = ar.y;
            As[buf ^ 1][acol + 2][arow] = ar.z; As[buf ^ 1][acol + 3][arow] = ar.w;
            *(float4*)&Bs[buf ^ 1][brow][bcol] = br;
        }
        __syncthreads();
        buf ^= 1;
    }

    // epilogue: add bias, write to scratch
    float bv[8];
    #pragma unroll
    for (int j = 0; j < 8; ++j) bv[j] = bias[n0 + tx * 8 + j];
    #pragma unroll
    for (int i = 0; i < 8; ++i) {
        float o[8];
        #pragma unroll
        for (int j = 0; j < 4; ++j) unpack2(acc[i][j], o[2 * j], o[2 * j + 1]);
        #pragma unroll
        for (int j = 0; j < 8; ++j) o[j] += bv[j];
        float* Cp = g_kqv + (size_t)(m0 + ty * 8 + i) * N3_ + n0 + tx * 8;
        *(float4*)Cp       = make_float4(o[0], o[1], o[2], o[3]);
        *(float4*)(Cp + 4) = make_float4(o[4], o[5], o[6], o[7]);
    }
}

// ============================================================================
// Kernel 2: fused flash-style attention per (b, h, 128-query tile).
// BK=64 key tiles; smem: Qs[128][65] natural, Kt[64][66] d-major (transposed),
// Vs[64][64] natural, Ps[128][65]. Running denominator in registers via
// shfl_xor over the 8 tx lanes. Output = (P@V)/den * mask_q.
// ============================================================================
#define BQ 128
#define BK 64

__global__ __launch_bounds__(256, 2) void attn_kernel(
    const float* __restrict__ masks, float* __restrict__ out)
{
    extern __shared__ float sm[];
    float* Qs = sm;                         // 128*65
    float* Kt = Qs + 128 * 65;              // 64*66
    float* Vs = Kt + 64 * 66;               // 64*64
    float* Ps = Vs + 64 * 64;               // 128*65
    float* mk = Ps + 128 * 65;              // 64

    const int tid = threadIdx.x;
    const int tx = tid & 7, ty = tid >> 3;    // tx: 0..7 (k/dd groups), ty: 0..31 (q groups)
    const int b = blockIdx.z, h = blockIdx.y;
    const int q0g = blockIdx.x * BQ;

    const float* Qg = g_kqv + (size_t)(b * S_ + q0g) * N3_ + D_ + h * HD_;
    const float* Kg = g_kqv + (size_t)(b * S_) * N3_ + h * HD_;
    const float* Vg = g_kqv + (size_t)(b * S_) * N3_ + 2 * D_ + h * HD_;

    // Load Q tile (128 x 64), natural layout, stride 65
    #pragma unroll
    for (int it = 0; it < 8; ++it) {
        int idx = it * 256 + tid;
        int q = idx >> 4, d4 = (idx & 15) * 4;
        float4 v = *(const float4*)(Qg + (size_t)q * N3_ + d4);
        Qs[q * 65 + d4 + 0] = v.x; Qs[q * 65 + d4 + 1] = v.y;
        Qs[q * 65 + d4 + 2] = v.z; Qs[q * 65 + d4 + 3] = v.w;
    }

    ull acc2[4][4];
    #pragma unroll
    for (int i = 0; i < 4; ++i)
        #pragma unroll
        for (int j = 0; j < 4; ++j) acc2[i][j] = 0ull;
    float den[4] = {0.f, 0.f, 0.f, 0.f};

    // Prefetch K/V tile 0 into registers
    float4 kr[4], vr[4]; float mreg;
    #pragma unroll
    for (int it = 0; it < 4; ++it) {
        int idx = it * 256 + tid;
        int k = idx >> 4, d4 = (idx & 15) * 4;
        kr[it] = *(const float4*)(Kg + (size_t)k * N3_ + d4);
        vr[it] = *(const float4*)(Vg + (size_t)k * N3_ + d4);
    }
    mreg = (tid < BK) ? masks[b * S_ + tid] : 0.f;

    for (int kt = 0; kt < S_ / BK; ++kt) {
        // Commit staged K (transposed) / V / mask to smem
        #pragma unroll
        for (int it = 0; it < 4; ++it) {
            int idx = it * 256 + tid;
            int k = idx >> 4, d4 = (idx & 15) * 4;
            Kt[(d4 + 0) * 66 + k] = kr[it].x;
            Kt[(d4 + 1) * 66 + k] = kr[it].y;
            Kt[(d4 + 2) * 66 + k] = kr[it].z;
            Kt[(d4 + 3) * 66 + k] = kr[it].w;
            *(float4*)&Vs[k * 64 + d4] = vr[it];
        }
        if (tid < BK) mk[tid] = mreg;
        __syncthreads();

        // Score GEMM: s[4 q][8 k] over d=64, f32x2 pairs along k
        ull s2[4][4];
        #pragma unroll
        for (int i = 0; i < 4; ++i)
            #pragma unroll
            for (int j = 0; j < 4; ++j) s2[i][j] = 0ull;

        #pragma unroll 8
        for (int dd = 0; dd < HD_; ++dd) {
            ull b2[4];
            #pragma unroll
            for (int j = 0; j < 4; ++j)
                b2[j] = *(const ull*)&Kt[dd * 66 + tx * 8 + 2 * j];
            #pragma unroll
            for (int i = 0; i < 4; ++i) {
                float a = Qs[(ty * 4 + i) * 65 + dd];
                ull ad = pack2(a, a);
                #pragma unroll
                for (int j = 0; j < 4; ++j) s2[i][j] = fma2(ad, b2[j], s2[i][j]);
            }
        }

        // Epilogue: p = exp(clip(elu(s))) * mask_k ; rowsum + write Ps
        float r[4];
        #pragma unroll
        for (int i = 0; i < 4; ++i) {
            r[i] = 0.f;
            #pragma unroll
            for (int j = 0; j < 4; ++j) {
                float lo, hi; unpack2(s2[i][j], lo, hi);
                float e0 = lo > 0.f ? fminf(lo, 10.f) : (__expf(lo) - 1.f);
                float e1 = hi > 0.f ? fminf(hi, 10.f) : (__expf(hi) - 1.f);
                float p0 = __expf(e0) * mk[tx * 8 + 2 * j];
                float p1 = __expf(e1) * mk[tx * 8 + 2 * j + 1];
                Ps[(ty * 4 + i) * 65 + tx * 8 + 2 * j]     = p0;
                Ps[(ty * 4 + i) * 65 + tx * 8 + 2 * j + 1] = p1;
                r[i] += p0 + p1;
            }
        }
        // Reduce rowsums across the 8 tx lanes (lane bits 0..2)
        #pragma unroll
        for (int i = 0; i < 4; ++i) {
            float v = r[i];
            v += __shfl_xor_sync(0xffffffffu, v, 1);
            v += __shfl_xor_sync(0xffffffffu, v, 2);
            v += __shfl_xor_sync(0xffffffffu, v, 4);
            den[i] += v;
        }
        __syncthreads();

        // Prefetch next K/V tile (LDG latency hidden under PV GEMM)
        if (kt + 1 < S_ / BK) {
            #pragma unroll
            for (int it = 0; it < 4; ++it) {
                int idx = it * 256 + tid;
                int k = idx >> 4, d4 = (idx & 15) * 4;
                kr[it] = *(const float4*)(Kg + (size_t)((kt + 1) * BK + k) * N3_ + d4);
                vr[it] = *(const float4*)(Vg + (size_t)((kt + 1) * BK + k) * N3_ + d4);
            }
            mreg = (tid < BK) ? masks[b * S_ + (kt + 1) * BK + tid] : 0.f;
        }

        // PV GEMM: acc[4 q][8 dd] += P[q][kk] * V[kk][dd]
        #pragma unroll 4
        for (int kk = 0; kk < BK; ++kk) {
            ull v2[4];
            #pragma unroll
            for (int j = 0; j < 4; ++j)
                v2[j] = *(const ull*)&Vs[kk * 64 + tx * 8 + 2 * j];
            #pragma unroll
            for (int i = 0; i < 4; ++i) {
                float p = Ps[(ty * 4 + i) * 65 + kk];
                ull pd = pack2(p, p);
                #pragma unroll
                for (int j = 0; j < 4; ++j) acc2[i][j] = fma2(pd, v2[j], acc2[i][j]);
            }
        }
        __syncthreads();
    }

    // Writeback: out = acc/den * mask_q
    #pragma unroll
    for (int i = 0; i < 4; ++i) {
        int q = q0g + ty * 4 + i;
        float scale = masks[b * S_ + q] / den[i];
        float o[8];
        #pragma unroll
        for (int j = 0; j < 4; ++j) unpack2(acc2[i][j], o[2 * j], o[2 * j + 1]);
        float* op = out + (size_t)(b * S_ + q) * D_ + h * HD_ + tx * 8;
        *(float4*)op       = make_float4(o[0] * scale, o[1] * scale, o[2] * scale, o[3] * scale);
        *(float4*)(op + 4) = make_float4(o[4] * scale, o[5] * scale, o[6] * scale, o[7] * scale);
    }
}

// ============================================================================
// Launch
// ============================================================================
extern "C" void kernel_launch(void* const* d_in, const int* in_sizes, int n_in,
                              void* d_out, int out_size)
{
    const float *inp = nullptr, *msk = nullptr, *W = nullptr, *bias = nullptr;
    for (int i = 0; i < n_in; ++i) {
        switch (in_sizes[i]) {
            case M_ * D_:   inp  = (const float*)d_in[i]; break;  // inputs  [2,2048,1024]
            case B_ * S_:   msk  = (const float*)d_in[i]; break;  // masks   [2,2048]
            case D_ * N3_:  W    = (const float*)d_in[i]; break;  // W       [1024,3072]
            case N3_:       bias = (const float*)d_in[i]; break;  // b       [3072]
        }
    }

    cudaFuncSetAttribute(attn_kernel,
                         cudaFuncAttributeMaxDynamicSharedMemorySize, 100096);

    dim3 g1(N3_ / 128, M_ / 128);          // (24, 32)
    gemm_kqv_kernel<<<g1, 256>>>(inp, W, bias);

    dim3 g2(S_ / BQ, H_, B_);              // (16, 16, 2)
    attn_kernel<<<g2, 256, 100096>>>(msk, (float*)d_out);
}

// round 2
// speedup vs baseline: 1.0014x; 1.0014x over previous
#include <cuda_runtime.h>

// Problem constants
#define B_  2
#define S_  2048
#define D_  1024
#define H_  16
#define HD_ 64
#define N3_ 3072
#define M_  (B_ * S_)   // 4096

// Scratch for the fused KQV projection output: [M_, 3072], layout [3][H][64] per row.
__device__ float g_kqv[(size_t)M_ * N3_];

typedef unsigned long long ull;

__device__ __forceinline__ ull pack2(float lo, float hi) {
    ull r; asm("mov.b64 %0, {%1,%2};" : "=l"(r) : "f"(lo), "f"(hi)); return r;
}
__device__ __forceinline__ void unpack2(ull v, float& lo, float& hi) {
    asm("mov.b64 {%0,%1}, %2;" : "=f"(lo), "=f"(hi) : "l"(v));
}
__device__ __forceinline__ ull fma2(ull a, ull b, ull c) {
    ull d; asm("fma.rn.f32x2 %0, %1, %2, %3;" : "=l"(d) : "l"(a), "l"(b), "l"(c)); return d;
}

// ============================================================================
// Kernel 1: C[4096,3072] = A[4096,1024] @ W[1024,3072] + bias
// 128x128 block tile, K-step 8, 256 threads, 8x8 microtile via f32x2,
// double-buffered smem (1 sync per K-iteration).
// ============================================================================
__global__ __launch_bounds__(256, 2) void gemm_kqv_kernel(
    const float* __restrict__ A, const float* __restrict__ W,
    const float* __restrict__ bias)
{
    __shared__ float As[2][8][132];   // transposed A tile: As[kk][m]
    __shared__ float Bs[2][8][128];   // Bs[kk][n]

    const int tid = threadIdx.x;
    const int tx = tid & 15, ty = tid >> 4;
    const int m0 = blockIdx.y * 128, n0 = blockIdx.x * 128;

    const int arow = tid >> 1, acol = (tid & 1) * 4;   // A: 128x8 tile
    const int brow = tid >> 5, bcol = (tid & 31) * 4;  // B: 8x128 tile

    const float* Ap = A + (size_t)(m0 + arow) * D_ + acol;
    const float* Wp = W + (size_t)brow * N3_ + n0 + bcol;

    // stage tile 0
    float4 ar = *(const float4*)Ap;
    float4 br = *(const float4*)Wp;
    As[0][acol + 0][arow] = ar.x; As[0][acol + 1][arow] = ar.y;
    As[0][acol + 2][arow] = ar.z; As[0][acol + 3][arow] = ar.w;
    *(float4*)&Bs[0][brow][bcol] = br;
    __syncthreads();

    ull acc[8][4];
    #pragma unroll
    for (int i = 0; i < 8; ++i)
        #pragma unroll
        for (int j = 0; j < 4; ++j) acc[i][j] = 0ull;

    int buf = 0;
    for (int kt = 0; kt < D_ / 8; ++kt) {
        if (kt + 1 < D_ / 8) {
            ar = *(const float4*)(Ap + (kt + 1) * 8);
            br = *(const float4*)(Wp + (size_t)(kt + 1) * 8 * N3_);
        }
        #pragma unroll
        for (int kk = 0; kk < 8; ++kk) {
            float4 a0 = *(const float4*)&As[buf][kk][ty * 8];
            float4 a1 = *(const float4*)&As[buf][kk][ty * 8 + 4];
            ull b2[4];
            #pragma unroll
            for (int j = 0; j < 4; ++j)
                b2[j] = *(const ull*)&Bs[buf][kk][tx * 8 + 2 * j];
            float av[8] = {a0.x, a0.y, a0.z, a0.w, a1.x, a1.y, a1.z, a1.w};
            #pragma unroll
            for (int i = 0; i < 8; ++i) {
                ull ad = pack2(av[i], av[i]);
                #pragma unroll
                for (int j = 0; j < 4; ++j) acc[i][j] = fma2(ad, b2[j], acc[i][j]);
            }
        }
        if (kt + 1 < D_ / 8) {
            As[buf ^ 1][acol + 0][arow] = ar.x; As[buf ^ 1][acol + 1][arow] = ar.y;
            As[buf ^ 1][acol + 2][arow] = ar.z; As[buf ^ 1][acol + 3][arow] = ar.w;
            *(float4*)&Bs[buf ^ 1][brow][bcol] = br;
        }
        __syncthreads();
        buf ^= 1;
    }

    // epilogue: add bias, write to scratch
    float bv[8];
    #pragma unroll
    for (int j = 0; j < 8; ++j) bv[j] = bias[n0 + tx * 8 + j];
    #pragma unroll
    for (int i = 0; i < 8; ++i) {
        float o[8];
        #pragma unroll
        for (int j = 0; j < 4; ++j) unpack2(acc[i][j], o[2 * j], o[2 * j + 1]);
        #pragma unroll
        for (int j = 0; j < 8; ++j) o[j] += bv[j];
        float* Cp = g_kqv + (size_t)(m0 + ty * 8 + i) * N3_ + n0 + tx * 8;
        *(float4*)Cp       = make_float4(o[0], o[1], o[2], o[3]);
        *(float4*)(Cp + 4) = make_float4(o[4], o[5], o[6], o[7]);
    }
}

// ============================================================================
// Kernel 2: fused flash-style attention per (b, h, 128-query tile).
// BK=64 key tiles; smem: Qs[128][65] natural, Kt[64][66] d-major (transposed),
// Vs[64][64] natural, Ps[128][65]. Running denominator in registers via
// shfl_xor over the 8 tx lanes. Output = (P@V)/den * mask_q.
// ============================================================================
#define BQ 128
#define BK 64

__global__ __launch_bounds__(256, 2) void attn_kernel(
    const float* __restrict__ masks, float* __restrict__ out)
{
    extern __shared__ float sm[];
    float* Qs = sm;                         // 128*65
    float* Kt = Qs + 128 * 65;              // 64*66
    float* Vs = Kt + 64 * 66;               // 64*64
    float* Ps = Vs + 64 * 64;               // 128*65
    float* mk = Ps + 128 * 65;              // 64

    const int tid = threadIdx.x;
    const int tx = tid & 7, ty = tid >> 3;    // tx: 0..7 (k/dd groups), ty: 0..31 (q groups)
    const int b = blockIdx.z, h = blockIdx.y;
    const int q0g = blockIdx.x * BQ;

    const float* Qg = g_kqv + (size_t)(b * S_ + q0g) * N3_ + D_ + h * HD_;
    const float* Kg = g_kqv + (size_t)(b * S_) * N3_ + h * HD_;
    const float* Vg = g_kqv + (size_t)(b * S_) * N3_ + 2 * D_ + h * HD_;

    // Load Q tile (128 x 64), natural layout, stride 65
    #pragma unroll
    for (int it = 0; it < 8; ++it) {
        int idx = it * 256 + tid;
        int q = idx >> 4, d4 = (idx & 15) * 4;
        float4 v = *(const float4*)(Qg + (size_t)q * N3_ + d4);
        Qs[q * 65 + d4 + 0] = v.x; Qs[q * 65 + d4 + 1] = v.y;
        Qs[q * 65 + d4 + 2] = v.z; Qs[q * 65 + d4 + 3] = v.w;
    }

    ull acc2[4][4];
    #pragma unroll
    for (int i = 0; i < 4; ++i)
        #pragma unroll
        for (int j = 0; j < 4; ++j) acc2[i][j] = 0ull;
    float den[4] = {0.f, 0.f, 0.f, 0.f};

    // Prefetch K/V tile 0 into registers
    float4 kr[4], vr[4]; float mreg;
    #pragma unroll
    for (int it = 0; it < 4; ++it) {
        int idx = it * 256 + tid;
        int k = idx >> 4, d4 = (idx & 15) * 4;
        kr[it] = *(const float4*)(Kg + (size_t)k * N3_ + d4);
        vr[it] = *(const float4*)(Vg + (size_t)k * N3_ + d4);
    }
    mreg = (tid < BK) ? masks[b * S_ + tid] : 0.f;

    for (int kt = 0; kt < S_ / BK; ++kt) {
        // Commit staged K (transposed) / V / mask to smem
        #pragma unroll
        for (int it = 0; it < 4; ++it) {
            int idx = it * 256 + tid;
            int k = idx >> 4, d4 = (idx & 15) * 4;
            Kt[(d4 + 0) * 66 + k] = kr[it].x;
            Kt[(d4 + 1) * 66 + k] = kr[it].y;
            Kt[(d4 + 2) * 66 + k] = kr[it].z;
            Kt[(d4 + 3) * 66 + k] = kr[it].w;
            *(float4*)&Vs[k * 64 + d4] = vr[it];
        }
        if (tid < BK) mk[tid] = mreg;
        __syncthreads();

        // Score GEMM: s[4 q][8 k] over d=64, f32x2 pairs along k
        ull s2[4][4];
        #pragma unroll
        for (int i = 0; i < 4; ++i)
            #pragma unroll
            for (int j = 0; j < 4; ++j) s2[i][j] = 0ull;

        #pragma unroll 8
        for (int dd = 0; dd < HD_; ++dd) {
            ull b2[4];
            #pragma unroll
            for (int j = 0; j < 4; ++j)
                b2[j] = *(const ull*)&Kt[dd * 66 + tx * 8 + 2 * j];
            #pragma unroll
            for (int i = 0; i < 4; ++i) {
                float a = Qs[(ty * 4 + i) * 65 + dd];
                ull ad = pack2(a, a);
                #pragma unroll
                for (int j = 0; j < 4; ++j) s2[i][j] = fma2(ad, b2[j], s2[i][j]);
            }
        }

        // Epilogue: p = exp(clip(elu(s))) * mask_k ; rowsum + write Ps
        float r[4];
        #pragma unroll
        for (int i = 0; i < 4; ++i) {
            r[i] = 0.f;
            #pragma unroll
            for (int j = 0; j < 4; ++j) {
                float lo, hi; unpack2(s2[i][j], lo, hi);
                float e0 = lo > 0.f ? fminf(lo, 10.f) : (__expf(lo) - 1.f);
                float e1 = hi > 0.f ? fminf(hi, 10.f) : (__expf(hi) - 1.f);
                float p0 = __expf(e0) * mk[tx * 8 + 2 * j];
                float p1 = __expf(e1) * mk[tx * 8 + 2 * j + 1];
                Ps[(ty * 4 + i) * 65 + tx * 8 + 2 * j]     = p0;
                Ps[(ty * 4 + i) * 65 + tx * 8 + 2 * j + 1] = p1;
                r[i] += p0 + p1;
            }
        }
        // Reduce rowsums across the 8 tx lanes (lane bits 0..2)
        #pragma unroll
        for (int i = 0; i < 4; ++i) {
            float v = r[i];
            v += __shfl_xor_sync(0xffffffffu, v, 1);
            v += __shfl_xor_sync(0xffffffffu, v, 2);
            v += __shfl_xor_sync(0xffffffffu, v, 4);
            den[i] += v;
        }
        __syncthreads();

        // Prefetch next K/V tile (LDG latency hidden under PV GEMM)
        if (kt + 1 < S_ / BK) {
            #pragma unroll
            for (int it = 0; it < 4; ++it) {
                int idx = it * 256 + tid;
                int k = idx >> 4, d4 = (idx & 15) * 4;
                kr[it] = *(const float4*)(Kg + (size_t)((kt + 1) * BK + k) * N3_ + d4);
                vr[it] = *(const float4*)(Vg + (size_t)((kt + 1) * BK + k) * N3_ + d4);
            }
            mreg = (tid < BK) ? masks[b * S_ + (kt + 1) * BK + tid] : 0.f;
        }

        // PV GEMM: acc[4 q][8 dd] += P[q][kk] * V[kk][dd]
        #pragma unroll 4
        for (int kk = 0; kk < BK; ++kk) {
            ull v2[4];
            #pragma unroll
            for (int j = 0; j < 4; ++j)
                v2[j] = *(const ull*)&Vs[kk * 64 + tx * 8 + 2 * j];
            #pragma unroll
            for (int i = 0; i < 4; ++i) {
                float p = Ps[(ty * 4 + i) * 65 + kk];
                ull pd = pack2(p, p);
                #pragma unroll
                for (int j = 0; j < 4; ++j) acc2[i][j] = fma2(pd, v2[j], acc2[i][j]);
            }
        }
        __syncthreads();
    }

    // Writeback: out = acc/den * mask_q
    #pragma unroll
    for (int i = 0; i < 4; ++i) {
        int q = q0g + ty * 4 + i;
        float scale = masks[b * S_ + q] / den[i];
        float o[8];
        #pragma unroll
        for (int j = 0; j < 4; ++j) unpack2(acc2[i][j], o[2 * j], o[2 * j + 1]);
        float* op = out + (size_t)(b * S_ + q) * D_ + h * HD_ + tx * 8;
        *(float4*)op       = make_float4(o[0] * scale, o[1] * scale, o[2] * scale, o[3] * scale);
        *(float4*)(op + 4) = make_float4(o[4] * scale, o[5] * scale, o[6] * scale, o[7] * scale);
    }
}

// ============================================================================
// Launch
// ============================================================================
extern "C" void kernel_launch(void* const* d_in, const int* in_sizes, int n_in,
                              void* d_out, int out_size)
{
    const float *inp = nullptr, *msk = nullptr, *W = nullptr, *bias = nullptr;
    for (int i = 0; i < n_in; ++i) {
        switch (in_sizes[i]) {
            case M_ * D_:   inp  = (const float*)d_in[i]; break;  // inputs  [2,2048,1024]
            case B_ * S_:   msk  = (const float*)d_in[i]; break;  // masks   [2,2048]
            case D_ * N3_:  W    = (const float*)d_in[i]; break;  // W       [1024,3072]
            case N3_:       bias = (const float*)d_in[i]; break;  // b       [3072]
        }
    }

    cudaFuncSetAttribute(attn_kernel,
                         cudaFuncAttributeMaxDynamicSharedMemorySize, 100096);

    dim3 g1(N3_ / 128, M_ / 128);          // (24, 32)
    gemm_kqv_kernel<<<g1, 256>>>(inp, W, bias);

    dim3 g2(S_ / BQ, H_, B_);              // (16, 16, 2)
    attn_kernel<<<g2, 256, 100096>>>(msk, (float*)d_out);
}